// round 3
// baseline (speedup 1.0000x reference)
#include <cuda_runtime.h>
#include <cuda_bf16.h>

// HMM forward (log-space output) via linear-domain recurrence with
// exponent-bit rescaling. See analysis above.
//
//   inputs: Y int32 [N,T], mask f32 [N,T], log_pi f32 [4,1],
//           log_A f32 [4,4], log_B f32 [4,NV]
//   output: alphas f32 [N,4,T]

#define TT    512            // T (hardcoded; N derived from in_sizes)
#define TC    32             // timesteps per chunk
#define NCH   (TT / TC)
#define BLK   128            // threads per block = sequences per block (max)
#define GRID  148            // one block per SM, single wave
#define MAXV  8192           // vocab capacity for static table

// exp(log_B) transposed: one float4 per vocab id = all 4 states' linear emissions.
__device__ float4 g_Bt[MAXV];

__global__ void hmm_prep_kernel(const float* __restrict__ logB, int NV) {
    int i = blockIdx.x * blockDim.x + threadIdx.x;
    if (i < NV) {
        float4 v;
        v.x = expf(logB[0 * NV + i]);
        v.y = expf(logB[1 * NV + i]);
        v.z = expf(logB[2 * NV + i]);
        v.w = expf(logB[3 * NV + i]);
        g_Bt[i] = v;
    }
}

// smem layout (dynamic):
//   float4 buf[BLK][33]   : alpha output staging (padded, conflict-free)
//   int    yb [BLK][33]   : Y chunk
//   float  mb [BLK][33]   : mask chunk
#define SMEM_BYTES (BLK * 33 * (int)sizeof(float4) + BLK * 33 * 4 + BLK * 33 * 4)

__global__ __launch_bounds__(BLK, 1) void hmm_kernel(
    const int*   __restrict__ Y,
    const float* __restrict__ mask,
    const float* __restrict__ logpi,
    const float* __restrict__ logA,
    const float* __restrict__ logB,
    float*       __restrict__ out,
    int N, int NV)
{
    extern __shared__ char smem[];
    float4* buf = (float4*)smem;
    int*    yb  = (int*)(smem + BLK * 33 * sizeof(float4));
    float*  mb  = (float*)(yb + BLK * 33);

    const int tid  = threadIdx.x;
    const int lane = tid & 31;
    const int warp = tid >> 5;

    // Balanced contiguous sequence ranges across GRID blocks.
    const long long bb = blockIdx.x;
    const int base = (int)((bb * (long long)N) / GRID);
    const int end  = (int)(((bb + 1) * (long long)N) / GRID);
    const int cnt  = end - base;
    const bool active = (tid < cnt);

    const float LN2 = 0.69314718055994530942f;
    const float L2E = 1.44269504088896340736f;

    // Linear-domain transition matrix in registers. exp(-1000) == 0.0f exactly,
    // so structural zeros are handled by the dense matvec with no assumptions.
    float A[16];
#pragma unroll
    for (int i = 0; i < 16; i++) A[i] = expf(__ldg(&logA[i]));

    // Recurrence state: scaled linear probs p[4], log-offset c (natural log),
    // previous natural-log alphas ap[4] (for the mask blend path).
    float p0 = 0.f, p1 = 0.f, p2 = 0.f, p3 = 0.f, c = 0.f;
    float ap0 = 0.f, ap1 = 0.f, ap2 = 0.f, ap3 = 0.f;

    for (int ch = 0; ch < NCH; ch++) {
        const int t0 = ch * TC;

        // --- stage Y/mask chunk (warp-local rows, coalesced 128B lines) ---
#pragma unroll 1
        for (int q = 0; q < 32; q++) {
            int row = (warp << 5) + q;
            if (row < cnt) {
                int g = (base + row) * TT + t0 + lane;
                yb[row * 33 + lane] = Y[g];
                mb[row * 33 + lane] = mask[g];
            }
        }
        __syncwarp();

        int jstart = 0;
        if (ch == 0) {
            // t = 0: alpha0 = log_pi + log_B[:, y0]  (exact, from inputs)
            int y0 = active ? yb[tid * 33 + 0] : 0;
            float a0 = __ldg(&logpi[0]) + __ldg(&logB[0 * NV + y0]);
            float a1 = __ldg(&logpi[1]) + __ldg(&logB[1 * NV + y0]);
            float a2 = __ldg(&logpi[2]) + __ldg(&logB[2 * NV + y0]);
            float a3 = __ldg(&logpi[3]) + __ldg(&logB[3 * NV + y0]);
            buf[tid * 33 + 0] = make_float4(a0, a1, a2, a3);
            c = fmaxf(fmaxf(a0, a1), fmaxf(a2, a3));
            p0 = exp2f((a0 - c) * L2E);
            p1 = exp2f((a1 - c) * L2E);
            p2 = exp2f((a2 - c) * L2E);
            p3 = exp2f((a3 - c) * L2E);
            ap0 = a0; ap1 = a1; ap2 = a2; ap3 = a3;
            jstart = 1;
        }

        // prime emission prefetch
        int yy = active ? yb[tid * 33 + jstart] : 0;
        float4 ecur = __ldg(&g_Bt[yy]);

#pragma unroll 4
        for (int j = jstart; j < TC; j++) {
            // prefetch next step's emission (off critical path; L1-resident table)
            int jn = (j + 1 < TC) ? (j + 1) : (TC - 1);
            int yn = active ? yb[tid * 33 + jn] : 0;
            float4 en = __ldg(&g_Bt[yn]);
            float4 e = ecur;

            // q[s] = (sum_p p[p] * A[p][s]) * e[s]   (dense 4x4 matvec)
            float q0 = p0 * A[0];
            q0 = fmaf(p1, A[4],  q0); q0 = fmaf(p2, A[8],  q0); q0 = fmaf(p3, A[12], q0); q0 *= e.x;
            float q1 = p0 * A[1];
            q1 = fmaf(p1, A[5],  q1); q1 = fmaf(p2, A[9],  q1); q1 = fmaf(p3, A[13], q1); q1 *= e.y;
            float q2 = p0 * A[2];
            q2 = fmaf(p1, A[6],  q2); q2 = fmaf(p2, A[10], q2); q2 = fmaf(p3, A[14], q2); q2 *= e.z;
            float q3 = p0 * A[3];
            q3 = fmaf(p1, A[7],  q3); q3 = fmaf(p2, A[11], q3); q3 = fmaf(p3, A[15], q3); q3 *= e.w;

            // power-of-2 rescale from exponent bits (no MUFU, exact offset)
            float mx = fmaxf(fmaxf(q0, q1), fmaxf(q2, q3));
            int   eb = __float_as_int(mx) >> 23;             // biased exponent (mx > 0)
            float scale = __int_as_float((254 - eb) << 23);  // 2^{-E}
            float Ef = (float)(eb - 127);

            // outputs: alpha[s] = log2(q[s]) * ln2 + c
            float an0 = fmaf(__log2f(q0), LN2, c);
            float an1 = fmaf(__log2f(q1), LN2, c);
            float an2 = fmaf(__log2f(q2), LN2, c);
            float an3 = fmaf(__log2f(q3), LN2, c);

            float m = active ? mb[tid * 33 + j] : 1.0f;
            if (m == 1.0f) {
                // fast path: commit rescaled state
                c  = fmaf(Ef, LN2, c);
                p0 = q0 * scale; p1 = q1 * scale; p2 = q2 * scale; p3 = q3 * scale;
            } else {
                // general mask blend: alpha = m*a_t + (1-m)*alpha_prev,
                // then rebuild (p, c) to match the blended alphas.
                an0 = fmaf(m, an0 - ap0, ap0);
                an1 = fmaf(m, an1 - ap1, ap1);
                an2 = fmaf(m, an2 - ap2, ap2);
                an3 = fmaf(m, an3 - ap3, ap3);
                float cm = fmaxf(fmaxf(an0, an1), fmaxf(an2, an3));
                c  = cm;
                p0 = exp2f((an0 - cm) * L2E);
                p1 = exp2f((an1 - cm) * L2E);
                p2 = exp2f((an2 - cm) * L2E);
                p3 = exp2f((an3 - cm) * L2E);
            }
            ap0 = an0; ap1 = an1; ap2 = an2; ap3 = an3;

            buf[tid * 33 + j] = make_float4(an0, an1, an2, an3);
            ecur = en;
        }
        __syncwarp();

        // --- coalesced writeout: per (seq,state) a contiguous 128B line ---
#pragma unroll 1
        for (int q = 0; q < 32; q++) {
            int row = (warp << 5) + q;
            if (row < cnt) {
                float4 v = buf[row * 33 + lane];   // lane = time within chunk
                int o = (base + row) * (4 * TT) + t0 + lane;
                out[o]          = v.x;
                out[o + TT]     = v.y;
                out[o + 2 * TT] = v.z;
                out[o + 3 * TT] = v.w;
            }
        }
        __syncwarp();
    }
}

extern "C" void kernel_launch(void* const* d_in, const int* in_sizes, int n_in,
                              void* d_out, int out_size) {
    const int*   Y     = (const int*)  d_in[0];
    const float* mask  = (const float*)d_in[1];
    const float* logpi = (const float*)d_in[2];
    const float* logA  = (const float*)d_in[3];
    const float* logB  = (const float*)d_in[4];
    float*       out   = (float*)d_out;

    const int N  = in_sizes[0] / TT;      // Y is [N, T]
    const int NV = in_sizes[4] / 4;       // log_B is [4, NV]

    cudaFuncSetAttribute(hmm_kernel,
                         cudaFuncAttributeMaxDynamicSharedMemorySize, SMEM_BYTES);

    hmm_prep_kernel<<<(NV + 127) / 128, 128>>>(logB, NV);
    hmm_kernel<<<GRID, BLK, SMEM_BYTES>>>(Y, mask, logpi, logA, logB, out, N, NV);
}